// round 3
// baseline (speedup 1.0000x reference)
#include <cuda_runtime.h>
#include <math.h>

#define D        128
#define NRBF     20
#define MAX_ATOMS 40960

// Scratch (alloc-free: __device__ globals)
__device__ __align__(16) float g_h[MAX_ATOMS * D];      // 20.5 MB
__device__ __align__(16) float g_agg[MAX_ATOMS * D];    // 20.5 MB
__device__ __align__(16) float g_WT[2][D * D];          // transposed W_in / W_out

__device__ __forceinline__ float ssp(float x) {
    // softplus(x) - log(2), numerically stable: max(x,0) + log1p(exp(-|x|)) - ln2
    float e = __expf(-fabsf(x));
    return fmaxf(x, 0.0f) + log1pf(e) - 0.69314718056f;
}

// Transpose W_in and W_out (row-major [c][k] -> [k][c]) so GEMM smem loads are
// coalesced and conflict-free.
__global__ void prep_kernel(const float* __restrict__ Win, const float* __restrict__ Wout) {
    int t = blockIdx.x * blockDim.x + threadIdx.x;
    if (t < D * D) {
        int c = t >> 7, k = t & 127;
        g_WT[0][k * D + c] = Win[t];
        g_WT[1][k * D + c] = Wout[t];
    }
}

__global__ void zero_kernel(int n4) {
    int t = blockIdx.x * blockDim.x + threadIdx.x;
    if (t < n4) reinterpret_cast<float4*>(g_agg)[t] = make_float4(0.f, 0.f, 0.f, 0.f);
}

// Y[r][c] = (ACT? ssp : id)( sum_k X[r][k] * W[c][k] + b[c] ), W pre-transposed in g_WT[WIDX].
// MODE 0: X = param (x), Y = g_h, no activation.
// MODE 1: X = g_agg,     Y = param (d_out), shifted-softplus.
// Block: 256 threads = 8 warps; 32 rows/block; each warp computes 4 rows,
// each lane 4 output columns (float4). K tiled by 32 through smem.
template <int MODE>
__global__ void __launch_bounds__(256) gemm_kernel(const float* __restrict__ Xparam,
                                                   const float* __restrict__ bias,
                                                   float* __restrict__ Yparam,
                                                   int n_rows) {
    __shared__ __align__(16) float sW[32 * D];   // 16 KB
    __shared__ __align__(16) float sX[32 * D];   // 16 KB

    const float* __restrict__ X = (MODE == 0) ? Xparam : g_agg;
    float* __restrict__ Y       = (MODE == 0) ? g_h    : Yparam;
    const float* __restrict__ Wt = g_WT[MODE];

    int r0 = blockIdx.x * 32;
    if (r0 >= n_rows) return;
    int lane = threadIdx.x & 31;
    int warp = threadIdx.x >> 5;

    // Load 32 input rows (coalesced)
    for (int t = threadIdx.x; t < 32 * D; t += 256) {
        int r = r0 + (t >> 7);
        sX[t] = (r < n_rows) ? X[(size_t)r * D + (t & 127)] : 0.0f;
    }

    float acc[4][4];
    #pragma unroll
    for (int r = 0; r < 4; r++)
        #pragma unroll
        for (int c = 0; c < 4; c++) acc[r][c] = 0.0f;

    #pragma unroll
    for (int tile = 0; tile < 4; tile++) {
        __syncthreads();  // first pass: covers sX; later: protects sW reuse
        for (int t = threadIdx.x; t < 32 * D; t += 256)
            sW[t] = Wt[tile * 32 * D + t];   // already [k][c]: coalesced, conflict-free
        __syncthreads();

        #pragma unroll
        for (int k = 0; k < 32; k++) {
            float4 w = *reinterpret_cast<const float4*>(sW + k * D + 4 * lane);
            #pragma unroll
            for (int r = 0; r < 4; r++) {
                float xv = sX[(warp * 4 + r) * D + tile * 32 + k];  // smem broadcast
                acc[r][0] = fmaf(w.x, xv, acc[r][0]);
                acc[r][1] = fmaf(w.y, xv, acc[r][1]);
                acc[r][2] = fmaf(w.z, xv, acc[r][2]);
                acc[r][3] = fmaf(w.w, xv, acc[r][3]);
            }
        }
    }

    float4 b4 = *reinterpret_cast<const float4*>(bias + 4 * lane);
    #pragma unroll
    for (int r = 0; r < 4; r++) {
        int row = r0 + warp * 4 + r;
        if (row < n_rows) {
            float4 o;
            o.x = acc[r][0] + b4.x;
            o.y = acc[r][1] + b4.y;
            o.z = acc[r][2] + b4.z;
            o.w = acc[r][3] + b4.w;
            if (MODE == 1) { o.x = ssp(o.x); o.y = ssp(o.y); o.z = ssp(o.z); o.w = ssp(o.w); }
            *reinterpret_cast<float4*>(Y + (size_t)row * D + 4 * lane) = o;
        }
    }
}

// Fused pair kernel: per pair p (one warp, lane owns 4 contiguous channels):
//   Wij = ssp(f_ij[p] @ W_f^T + b_f) * rcut[p]
//   agg[idx_i[p]] += h[idx_j[p]] * Wij     (red.global.add.v4.f32)
__global__ void __launch_bounds__(256) pair_kernel(const float* __restrict__ f_ij,
                                                   const int* __restrict__ idx_i,
                                                   const int* __restrict__ idx_j,
                                                   const float* __restrict__ rcut,
                                                   const float* __restrict__ W_f,
                                                   const float* __restrict__ b_f,
                                                   int n_pairs) {
    __shared__ __align__(16) float sWf[NRBF * D];  // transposed [k][c], 10 KB
    __shared__ __align__(16) float sbf[D];

    for (int t = threadIdx.x; t < NRBF * D; t += blockDim.x) {
        int c = t / NRBF, k = t - c * NRBF;
        sWf[k * D + c] = W_f[t];
    }
    if (threadIdx.x < D) sbf[threadIdx.x] = b_f[threadIdx.x];
    __syncthreads();

    int lane = threadIdx.x & 31;
    int gw   = (blockIdx.x * blockDim.x + threadIdx.x) >> 5;
    int nw   = (gridDim.x * blockDim.x) >> 5;

    const float4 b4 = *reinterpret_cast<const float4*>(sbf + 4 * lane);

    for (int p = gw; p < n_pairs; p += nw) {
        float fv = (lane < NRBF) ? f_ij[(size_t)p * NRBF + lane] : 0.0f;
        int i = idx_i[p];
        int j = idx_j[p];
        float rc = rcut[p];

        float4 acc = b4;
        #pragma unroll
        for (int k = 0; k < NRBF; k++) {
            float fk = __shfl_sync(0xffffffffu, fv, k);
            float4 w = *reinterpret_cast<const float4*>(sWf + k * D + 4 * lane);
            acc.x = fmaf(w.x, fk, acc.x);
            acc.y = fmaf(w.y, fk, acc.y);
            acc.z = fmaf(w.z, fk, acc.z);
            acc.w = fmaf(w.w, fk, acc.w);
        }
        acc.x = ssp(acc.x) * rc;
        acc.y = ssp(acc.y) * rc;
        acc.z = ssp(acc.z) * rc;
        acc.w = ssp(acc.w) * rc;

        const float4 h4 = *reinterpret_cast<const float4*>(g_h + (size_t)j * D + 4 * lane);
        float vx = h4.x * acc.x, vy = h4.y * acc.y, vz = h4.z * acc.z, vw = h4.w * acc.w;

        float* dst = g_agg + (size_t)i * D + 4 * lane;
        asm volatile("red.global.add.v4.f32 [%0], {%1,%2,%3,%4};"
                     :: "l"(dst), "f"(vx), "f"(vy), "f"(vz), "f"(vw)
                     : "memory");
    }
}

extern "C" void kernel_launch(void* const* d_in, const int* in_sizes, int n_in,
                              void* d_out, int out_size) {
    const float* x     = (const float*)d_in[0];
    const float* f_ij  = (const float*)d_in[1];
    const int*   idx_i = (const int*)  d_in[2];
    const int*   idx_j = (const int*)  d_in[3];
    const float* rcut  = (const float*)d_in[4];
    const float* W_in  = (const float*)d_in[5];
    const float* b_in  = (const float*)d_in[6];
    const float* W_f   = (const float*)d_in[7];
    const float* b_f   = (const float*)d_in[8];
    const float* W_out = (const float*)d_in[9];
    const float* b_out = (const float*)d_in[10];
    float* out = (float*)d_out;
    (void)n_in; (void)out_size;

    int n_atoms = in_sizes[0] / D;
    int n_pairs = in_sizes[2];

    // Transpose weights + zero accumulator (independent, cheap)
    prep_kernel<<<(D * D + 255) / 256, 256>>>(W_in, W_out);
    int n4 = (n_atoms * D) / 4;
    zero_kernel<<<(n4 + 255) / 256, 256>>>(n4);

    // h = x @ W_in^T + b_in   -> g_h
    int gblocks = (n_atoms + 31) / 32;
    gemm_kernel<0><<<gblocks, 256>>>(x, b_in, nullptr, n_atoms);

    // fused filter + gather + scatter-add -> g_agg  (single wave: 148 SMs * 8 blocks)
    pair_kernel<<<1184, 256>>>(f_ij, idx_i, idx_j, rcut, W_f, b_f, n_pairs);

    // out = ssp(g_agg @ W_out^T + b_out)
    gemm_kernel<1><<<gblocks, 256>>>(nullptr, b_out, out, n_atoms);
}